// round 7
// baseline (speedup 1.0000x reference)
#include <cuda_runtime.h>
#include <cstdint>

#define NUM_USER   4096
#define NUM_ITEM   16384
#define NUM_HIDDEN 64
#define BATCH      1024
#define SETLEN     50
#define NJ         (BATCH * SETLEN)              // 51200 scatter updates

#define PLANE      ((size_t)NUM_USER * NUM_ITEM) // 67,108,864 cells per plane

// Only persistent device state. INVARIANT: zero at the start of every
// launch / graph replay (label_kernel thread 0 resets it after use).
__device__ unsigned int g_nnz;

// ---------------------------------------------------------------------------
// Pass 1: NO arbitration needed for pred — duplicates of a cell share the
// same (u, it), hence the identical dot product; concurrent plain stores of
// identical bits are benign. Arbitration (for label) runs in the label
// plane: atomicMax with tag j+1 -> surviving tag = max j = last-write-wins
// in (b,l) row-major order (XLA scatter semantics). First toucher counts
// the unique cell for sum(mask). The dot has NO dependent scattered load
// in front of it: all 32 embed loads issue immediately (pure MLP).
// ---------------------------------------------------------------------------
__global__ void compute_kernel(const int*   __restrict__ idx_user,
                               const int*   __restrict__ item_sets,
                               const float* __restrict__ embed_user,
                               const float* __restrict__ embed_item,
                               float* __restrict__ out) {
    int j = blockIdx.x * blockDim.x + threadIdx.x;
    if (j >= NJ) return;
    int b = j / SETLEN;
    unsigned int u    = (unsigned int)__ldg(idx_user + b);
    unsigned int it   = (unsigned int)__ldg(item_sets + j);
    unsigned int cell = u * NUM_ITEM + it;

    // 64-dim dot, float4-vectorized, 4 independent partials for ILP.
    const float4* ur = (const float4*)(embed_user + (size_t)u  * NUM_HIDDEN);
    const float4* ir = (const float4*)(embed_item + (size_t)it * NUM_HIDDEN);
    float s0 = 0.f, s1 = 0.f, s2 = 0.f, s3 = 0.f;
#pragma unroll
    for (int k = 0; k < NUM_HIDDEN / 16; k++) {
        float4 a0 = ur[4*k+0], c0 = ir[4*k+0];
        float4 a1 = ur[4*k+1], c1 = ir[4*k+1];
        float4 a2 = ur[4*k+2], c2 = ir[4*k+2];
        float4 a3 = ur[4*k+3], c3 = ir[4*k+3];
        s0 = fmaf(a0.x,c0.x, fmaf(a0.y,c0.y, fmaf(a0.z,c0.z, fmaf(a0.w,c0.w, s0))));
        s1 = fmaf(a1.x,c1.x, fmaf(a1.y,c1.y, fmaf(a1.z,c1.z, fmaf(a1.w,c1.w, s1))));
        s2 = fmaf(a2.x,c2.x, fmaf(a2.y,c2.y, fmaf(a2.z,c2.z, fmaf(a2.w,c2.w, s2))));
        s3 = fmaf(a3.x,c3.x, fmaf(a3.y,c3.y, fmaf(a3.z,c3.z, fmaf(a3.w,c3.w, s3))));
    }
    float acc = (s0 + s1) + (s2 + s3);

    out[cell] = acc;                                 // pred: benign identical race

    int old = atomicMax((int*)(out + PLANE) + cell, j + 1);  // label tag
    if (old == 0) atomicAdd(&g_nnz, 1u);             // first toucher of cell
}

// ---------------------------------------------------------------------------
// Pass 2: tiny. The winner of each label cell (tag == j+1) overwrites the
// tag with its rating; every tagged cell has exactly one winner, so no tag
// bit-pattern survives. Thread 0 emits sparsity and restores g_nnz = 0.
// ---------------------------------------------------------------------------
__global__ void label_kernel(const int*   __restrict__ idx_user,
                             const int*   __restrict__ item_sets,
                             const float* __restrict__ ratings,
                             float* __restrict__ out) {
    int j = blockIdx.x * blockDim.x + threadIdx.x;
    if (j == 0) {
        out[2 * PLANE] = (float)((double)PLANE / (double)g_nnz);
        g_nnz = 0u;                                  // self-cleaning invariant
    }
    if (j >= NJ) return;

    int b = j / SETLEN;
    unsigned int u    = (unsigned int)__ldg(idx_user + b);
    unsigned int it   = (unsigned int)__ldg(item_sets + j);
    unsigned int cell = u * NUM_ITEM + it;

    if (((const int*)(out + PLANE))[cell] == j + 1)  // winner?
        out[PLANE + cell] = ratings[j];
}

// ---------------------------------------------------------------------------
// 3-node pipeline: 512MB zero-fill (the HBM floor) + two short passes that
// use the zeroed label plane itself as the arbitration array.
// ---------------------------------------------------------------------------
extern "C" void kernel_launch(void* const* d_in, const int* in_sizes, int n_in,
                              void* d_out, int out_size) {
    const int*   idx_user   = (const int*)  d_in[0];
    const int*   item_sets  = (const int*)  d_in[1];
    const float* rating     = (const float*)d_in[2];
    const float* embed_user = (const float*)d_in[3];
    const float* embed_item = (const float*)d_in[4];
    float* out = (float*)d_out;

    cudaMemsetAsync(out, 0, 2ull * PLANE * sizeof(float), 0);
    compute_kernel<<<(NJ + 255) / 256, 256>>>(idx_user, item_sets,
                                              embed_user, embed_item, out);
    label_kernel  <<<(NJ + 255) / 256, 256>>>(idx_user, item_sets, rating, out);
}

// round 9
// speedup vs baseline: 1.0036x; 1.0036x over previous
#include <cuda_runtime.h>
#include <cstdint>

#define NUM_USER   4096
#define NUM_ITEM   16384
#define NUM_HIDDEN 64
#define BATCH      1024
#define SETLEN     50
#define NJ         (BATCH * SETLEN)              // 51200 scatter updates

#define PLANE      ((size_t)NUM_USER * NUM_ITEM) // 67,108,864 cells per plane

// Only persistent device state. INVARIANT: zero at the start of every
// launch / graph replay (resolve_kernel thread 0 resets it after use).
__device__ unsigned int g_nnz;

// ---------------------------------------------------------------------------
// Pass 1 (tiny): arbitration ONLY. Thread j tags label[cell] with j+1 via
// atomicMax -> surviving tag = max j = last-write-wins in (b,l) row-major
// order (XLA scatter semantics). First toucher (old==0) counts the unique
// cell for sum(mask). Runs on the freshly-zeroed label plane.
// ---------------------------------------------------------------------------
__global__ void tag_kernel(const int* __restrict__ idx_user,
                           const int* __restrict__ item_sets,
                           float* __restrict__ out) {
    int j = blockIdx.x * blockDim.x + threadIdx.x;
    if (j >= NJ) return;
    int b = j / SETLEN;
    unsigned int u    = (unsigned int)__ldg(idx_user + b);
    unsigned int it   = (unsigned int)__ldg(item_sets + j);
    unsigned int cell = u * NUM_ITEM + it;

    int old = atomicMax((int*)(out + PLANE) + cell, j + 1);
    if (old == 0) atomicAdd(&g_nnz, 1u);
}

// ---------------------------------------------------------------------------
// Pass 2: dependency-free resolve.
//  - pred: duplicates of a cell share (u, it) -> identical dot product, so
//    EVERY thread computes it and plain-stores pred[cell]; concurrent
//    identical-bit stores are benign. No tag dependency in front of the dot.
//  - label: the tag load is issued in parallel with the 32 embed loads
//    (independent addresses; tag line is L2-hot from pass 1's atomics).
//    The unique winner (tag == j+1) overwrites the tag with its rating, so
//    no tag bit-pattern survives.
//  - thread 0 emits sparsity and restores g_nnz = 0 (pristine for replay).
// ---------------------------------------------------------------------------
__global__ void resolve_kernel(const int*   __restrict__ idx_user,
                               const int*   __restrict__ item_sets,
                               const float* __restrict__ ratings,
                               const float* __restrict__ embed_user,
                               const float* __restrict__ embed_item,
                               float* __restrict__ out) {
    int j = blockIdx.x * blockDim.x + threadIdx.x;
    if (j == 0) {
        out[2 * PLANE] = (float)((double)PLANE / (double)g_nnz);
        g_nnz = 0u;                              // self-cleaning invariant
    }
    if (j >= NJ) return;

    int b = j / SETLEN;
    unsigned int u    = (unsigned int)__ldg(idx_user + b);
    unsigned int it   = (unsigned int)__ldg(item_sets + j);
    unsigned int cell = u * NUM_ITEM + it;

    // Independent loads, all issued before any consumer: tag + rating + 32
    // embed vectors -> a single memory round trip covers everything.
    int   tag = ((const int*)(out + PLANE))[cell];
    float rat = __ldg(ratings + j);

    const float4* ur = (const float4*)(embed_user + (size_t)u  * NUM_HIDDEN);
    const float4* ir = (const float4*)(embed_item + (size_t)it * NUM_HIDDEN);
    float s0 = 0.f, s1 = 0.f, s2 = 0.f, s3 = 0.f;
#pragma unroll
    for (int k = 0; k < NUM_HIDDEN / 16; k++) {
        float4 a0 = ur[4*k+0], c0 = ir[4*k+0];
        float4 a1 = ur[4*k+1], c1 = ir[4*k+1];
        float4 a2 = ur[4*k+2], c2 = ir[4*k+2];
        float4 a3 = ur[4*k+3], c3 = ir[4*k+3];
        s0 = fmaf(a0.x,c0.x, fmaf(a0.y,c0.y, fmaf(a0.z,c0.z, fmaf(a0.w,c0.w, s0))));
        s1 = fmaf(a1.x,c1.x, fmaf(a1.y,c1.y, fmaf(a1.z,c1.z, fmaf(a1.w,c1.w, s1))));
        s2 = fmaf(a2.x,c2.x, fmaf(a2.y,c2.y, fmaf(a2.z,c2.z, fmaf(a2.w,c2.w, s2))));
        s3 = fmaf(a3.x,c3.x, fmaf(a3.y,c3.y, fmaf(a3.z,c3.z, fmaf(a3.w,c3.w, s3))));
    }
    float acc = (s0 + s1) + (s2 + s3);

    out[cell] = acc;                             // pred: benign identical race
    if (tag == j + 1)
        out[PLANE + cell] = rat;                 // label: unique winner
}

// ---------------------------------------------------------------------------
// 3-node pipeline: 512MB zero-fill (the HBM floor, ~80us) + arbitration
// pass + dependency-free resolve pass.
// ---------------------------------------------------------------------------
extern "C" void kernel_launch(void* const* d_in, const int* in_sizes, int n_in,
                              void* d_out, int out_size) {
    const int*   idx_user   = (const int*)  d_in[0];
    const int*   item_sets  = (const int*)  d_in[1];
    const float* rating     = (const float*)d_in[2];
    const float* embed_user = (const float*)d_in[3];
    const float* embed_item = (const float*)d_in[4];
    float* out = (float*)d_out;

    cudaMemsetAsync(out, 0, 2ull * PLANE * sizeof(float), 0);
    tag_kernel    <<<(NJ + 255) / 256, 256>>>(idx_user, item_sets, out);
    resolve_kernel<<<(NJ + 255) / 256, 256>>>(idx_user, item_sets, rating,
                                              embed_user, embed_item, out);
}

// round 10
// speedup vs baseline: 1.0544x; 1.0506x over previous
#include <cuda_runtime.h>
#include <cstdint>

#define NUM_USER   4096
#define NUM_ITEM   16384
#define NUM_HIDDEN 64
#define BATCH      1024
#define SETLEN     50
#define NJ         (BATCH * SETLEN)              // 51200 scatter updates

#define PLANE      ((size_t)NUM_USER * NUM_ITEM) // 67,108,864 cells per plane
#define LPJ        8                             // lanes per update j

// Only persistent device state. INVARIANT: zero at the start of every
// launch / graph replay (resolve_kernel resets it after use).
__device__ unsigned int g_nnz;

// ---------------------------------------------------------------------------
// Pass 1 (tiny): arbitration ONLY. Thread j tags label[cell] with j+1 via
// atomicMax -> surviving tag = max j = last-write-wins in (b,l) row-major
// order (XLA scatter semantics). First toucher (old==0) counts the unique
// cell for sum(mask). Runs on the freshly-zeroed label plane.
// ---------------------------------------------------------------------------
__global__ void tag_kernel(const int* __restrict__ idx_user,
                           const int* __restrict__ item_sets,
                           float* __restrict__ out) {
    int j = blockIdx.x * blockDim.x + threadIdx.x;
    if (j >= NJ) return;
    int b = j / SETLEN;
    unsigned int u    = (unsigned int)__ldg(idx_user + b);
    unsigned int it   = (unsigned int)__ldg(item_sets + j);
    unsigned int cell = u * NUM_ITEM + it;

    int old = atomicMax((int*)(out + PLANE) + cell, j + 1);
    if (old == 0) atomicAdd(&g_nnz, 1u);
}

// ---------------------------------------------------------------------------
// Pass 2: warp-split resolve — 8 lanes per update j (R9 showed resolve is
// occupancy-starved at 1 thread/j: 2.7 warps/SMSP, occ 16%, issue 3%).
// 409,600 threads -> ~21.6 warps/SMSP of latency cover.
//  - lanes 0..7 of a group each load 8 dims (2 float4 pairs), butterfly
//    shuffle-reduce within the 8-lane group.
//  - pred: stored unconditionally by lane 0 — duplicates of a cell share
//    (u, it) => identical dot, so the race writes identical bits (benign).
//  - label: lane 0 loads the tag early (independent of embed loads); the
//    unique winner (tag == j+1) overwrites the tag with its rating.
//  - global thread 0 emits sparsity and restores g_nnz = 0.
// ---------------------------------------------------------------------------
__global__ void resolve_kernel(const int*   __restrict__ idx_user,
                               const int*   __restrict__ item_sets,
                               const float* __restrict__ ratings,
                               const float* __restrict__ embed_user,
                               const float* __restrict__ embed_item,
                               float* __restrict__ out) {
    int t = blockIdx.x * blockDim.x + threadIdx.x;
    if (t == 0) {
        out[2 * PLANE] = (float)((double)PLANE / (double)g_nnz);
        g_nnz = 0u;                              // self-cleaning invariant
    }
    int j = t >> 3;                              // update index
    int r = t & (LPJ - 1);                       // lane within 8-group
    if (j >= NJ) return;

    int b = j / SETLEN;
    unsigned int u    = (unsigned int)__ldg(idx_user + b);
    unsigned int it   = (unsigned int)__ldg(item_sets + j);
    unsigned int cell = u * NUM_ITEM + it;

    // Lane 0 issues the scattered tag + rating loads up front, overlapped
    // with everyone's embed loads (all independent addresses).
    int   tag = 0;
    float rat = 0.f;
    if (r == 0) {
        tag = ((const int*)(out + PLANE))[cell];
        rat = __ldg(ratings + j);
    }

    // Each lane: 8 dims = 2 float4 pairs, 8 FMAs.
    const float4* ur = (const float4*)(embed_user + (size_t)u  * NUM_HIDDEN);
    const float4* ir = (const float4*)(embed_item + (size_t)it * NUM_HIDDEN);
    float4 a0 = ur[2*r+0], c0 = ir[2*r+0];
    float4 a1 = ur[2*r+1], c1 = ir[2*r+1];
    float s  = fmaf(a0.x,c0.x, fmaf(a0.y,c0.y, fmaf(a0.z,c0.z, a0.w*c0.w)));
    s       += fmaf(a1.x,c1.x, fmaf(a1.y,c1.y, fmaf(a1.z,c1.z, a1.w*c1.w)));

    // Butterfly reduce within the 8-lane group.
    s += __shfl_xor_sync(0xFFFFFFFFu, s, 4, LPJ);
    s += __shfl_xor_sync(0xFFFFFFFFu, s, 2, LPJ);
    s += __shfl_xor_sync(0xFFFFFFFFu, s, 1, LPJ);

    if (r == 0) {
        out[cell] = s;                           // pred: benign identical race
        if (tag == j + 1)
            out[PLANE + cell] = rat;             // label: unique winner
    }
}

// ---------------------------------------------------------------------------
// 3-node pipeline: 512MB zero-fill (the HBM floor, ~80us) + arbitration
// pass + warp-split resolve pass.
// ---------------------------------------------------------------------------
extern "C" void kernel_launch(void* const* d_in, const int* in_sizes, int n_in,
                              void* d_out, int out_size) {
    const int*   idx_user   = (const int*)  d_in[0];
    const int*   item_sets  = (const int*)  d_in[1];
    const float* rating     = (const float*)d_in[2];
    const float* embed_user = (const float*)d_in[3];
    const float* embed_item = (const float*)d_in[4];
    float* out = (float*)d_out;

    cudaMemsetAsync(out, 0, 2ull * PLANE * sizeof(float), 0);
    tag_kernel    <<<(NJ + 255) / 256, 256>>>(idx_user, item_sets, out);
    resolve_kernel<<<(NJ * LPJ + 255) / 256, 256>>>(idx_user, item_sets, rating,
                                                    embed_user, embed_item, out);
}